// round 15
// baseline (speedup 1.0000x reference)
#include <cuda_runtime.h>
#include <cuda_bf16.h>
#include <math.h>
#include <stdint.h>

#define BB 4
#define SS 2048
#define DD 2048
#define HH 16
#define HD 128
#define MM (BB*SS)   // 8192

// ---------------- scratch (device globals: allocation-free rule) -----------
__device__ __nv_bfloat16 g_qh[(size_t)BB*HH*SS*HD];
__device__ __nv_bfloat16 g_ql[(size_t)BB*HH*SS*HD];
__device__ __nv_bfloat16 g_kh[(size_t)BB*HH*SS*HD];
__device__ __nv_bfloat16 g_kl[(size_t)BB*HH*SS*HD];
__device__ __nv_bfloat16 g_vh[(size_t)BB*HH*SS*HD];
__device__ __nv_bfloat16 g_vl[(size_t)BB*HH*SS*HD];
__device__ __nv_bfloat16 g_xh[(size_t)MM*DD];
__device__ __nv_bfloat16 g_xl[(size_t)MM*DD];
__device__ __nv_bfloat16 g_wh[(size_t)4*DD*DD];
__device__ __nv_bfloat16 g_wl[(size_t)4*DD*DD];
__device__ __nv_bfloat16 g_ch[(size_t)MM*DD];
__device__ __nv_bfloat16 g_cl[(size_t)MM*DD];
__device__ float g_cos[SS*64];
__device__ float g_sin[SS*64];

// ---------------- helpers ----------------------------------------------------
__device__ __forceinline__ uint32_t smem_u32(const void* p) {
    uint32_t a;
    asm("{ .reg .u64 t; cvta.to.shared.u64 t, %1; cvt.u32.u64 %0, t; }"
        : "=r"(a) : "l"(p));
    return a;
}
__device__ __forceinline__ void cp16(uint32_t dst, const void* src) {
    asm volatile("cp.async.cg.shared.global [%0], [%1], 16;" :: "r"(dst), "l"(src));
}
#define CP_COMMIT() asm volatile("cp.async.commit_group;" ::: "memory")
#define CP_WAIT(n)  asm volatile("cp.async.wait_group %0;" :: "n"(n) : "memory")

__device__ __forceinline__ void mma16816(float* c, const uint32_t* a, const uint32_t* b) {
    asm volatile(
        "mma.sync.aligned.m16n8k16.row.col.f32.bf16.bf16.f32 "
        "{%0,%1,%2,%3}, {%4,%5,%6,%7}, {%8,%9}, {%0,%1,%2,%3};"
        : "+f"(c[0]), "+f"(c[1]), "+f"(c[2]), "+f"(c[3])
        : "r"(a[0]), "r"(a[1]), "r"(a[2]), "r"(a[3]), "r"(b[0]), "r"(b[1]));
}
__device__ __forceinline__ void mma2(float* c, const uint32_t* a, uint32_t b0, uint32_t b1) {
    asm volatile(
        "mma.sync.aligned.m16n8k16.row.col.f32.bf16.bf16.f32 "
        "{%0,%1,%2,%3}, {%4,%5,%6,%7}, {%8,%9}, {%0,%1,%2,%3};"
        : "+f"(c[0]), "+f"(c[1]), "+f"(c[2]), "+f"(c[3])
        : "r"(a[0]), "r"(a[1]), "r"(a[2]), "r"(a[3]), "r"(b0), "r"(b1));
}
__device__ __forceinline__ void ldsm_x4(uint32_t* r, uint32_t addr) {
    asm volatile("ldmatrix.sync.aligned.m8n8.x4.shared.b16 {%0,%1,%2,%3}, [%4];"
        : "=r"(r[0]), "=r"(r[1]), "=r"(r[2]), "=r"(r[3]) : "r"(addr));
}
__device__ __forceinline__ void ldsm_x4_t(uint32_t* r, uint32_t addr) {
    asm volatile("ldmatrix.sync.aligned.m8n8.x4.trans.shared.b16 {%0,%1,%2,%3}, [%4];"
        : "=r"(r[0]), "=r"(r[1]), "=r"(r[2]), "=r"(r[3]) : "r"(addr));
}
__device__ __forceinline__ uint32_t packbf(float lo, float hi) {
    uint32_t r;
    asm("cvt.rn.bf16x2.f32 %0, %1, %2;" : "=r"(r) : "f"(hi), "f"(lo));
    return r;
}
__device__ __forceinline__ void split2(float x, float y, uint32_t& hp, uint32_t& lp) {
    hp = packbf(x, y);
    float hx = __int_as_float(hp << 16);
    float hy = __int_as_float(hp & 0xFFFF0000u);
    lp = packbf(x - hx, y - hy);
}
// fast exp on FMA/ALU pipes (x <= ~0), rel err ~2e-6
__device__ __forceinline__ float fexp(float x) {
    float y = fmaxf(x * 1.4426950408889634f, -120.f);
    float t = y + 12582912.f;
    int n = __float_as_int(t) - 0x4B400000;
    float f = y - (t - 12582912.f);
    float p = 1.3333558146e-3f;
    p = fmaf(p, f, 9.6181291076e-3f);
    p = fmaf(p, f, 5.5504108665e-2f);
    p = fmaf(p, f, 2.4022650696e-1f);
    p = fmaf(p, f, 6.9314718056e-1f);
    p = fmaf(p, f, 1.0f);
    return p * __int_as_float((127 + n) << 23);
}

// ---------------- unified conversion kernel (x, 4 weights, rope) -------------
// 8 floats per thread -> 16B stores on all four output streams
__device__ __forceinline__ void split8(const float* in, __nv_bfloat16* hi,
                                       __nv_bfloat16* lo, int i) {
    float4 v0 = ((const float4*)in)[2 * i];
    float4 v1 = ((const float4*)in)[2 * i + 1];
    float a[8] = {v0.x, v0.y, v0.z, v0.w, v1.x, v1.y, v1.z, v1.w};
    __align__(16) __nv_bfloat16 h[8], l[8];
#pragma unroll
    for (int j = 0; j < 8; j++) {
        h[j] = __float2bfloat16(a[j]);
        l[j] = __float2bfloat16(a[j] - __bfloat162float(h[j]));
    }
    *(uint4*)&hi[(size_t)i * 8] = *(uint4*)h;
    *(uint4*)&lo[(size_t)i * 8] = *(uint4*)l;
}

#define XN8 (MM*DD/8)     // 2097152
#define WN8 (DD*DD/8)     // 524288 = 2^19
#define CVT_TOTAL (XN8 + 4*WN8 + SS*64)

__global__ void cvt_all_kernel(const float* __restrict__ x,
                               const float* __restrict__ wq, const float* __restrict__ wk,
                               const float* __restrict__ wv, const float* __restrict__ wo,
                               __nv_bfloat16* __restrict__ xh, __nv_bfloat16* __restrict__ xl,
                               __nv_bfloat16* __restrict__ wh, __nv_bfloat16* __restrict__ wl)
{
    int i = blockIdx.x * blockDim.x + threadIdx.x;
    if (i < XN8) { split8(x, xh, xl, i); return; }
    i -= XN8;
    if (i < 4 * WN8) {
        int wsel = i >> 19;
        int j = i & (WN8 - 1);
        const float* w = (wsel == 0) ? wq : (wsel == 1) ? wk : (wsel == 2) ? wv : wo;
        split8(w, wh + (size_t)wsel * DD * DD, wl + (size_t)wsel * DD * DD, j);
        return;
    }
    i -= 4 * WN8;
    if (i < SS * 64) {
        int s = i >> 6, p = i & 63;
        double invf = exp(-(double)p * (log(10000.0) / 64.0));
        float ang = (float)s * (float)invf;
        float sv, cv;
        sincosf(ang, &sv, &cv);
        g_cos[i] = cv;
        g_sin[i] = sv;
    }
}

// ---------------- shared GEMM mainloop (R12: 64x64 warp tile, two-phase B) ----
#define KSTG    32
#define TWORDS  2048                 // 128 rows * 16 words
#define SWORDS  (4*TWORDS)           // 8192 words = 32 KB per stage
#define GEMM_SMEM (3*SWORDS*4)       // 98304 bytes -> 2 CTAs/SM
#define NSTG    (DD/KSTG)            // 64
#define GEMM_THREADS 128

__device__ __forceinline__ void gemm_core(
    const __nv_bfloat16* __restrict__ src0, const __nv_bfloat16* __restrict__ src1,
    const __nv_bfloat16* __restrict__ src2, const __nv_bfloat16* __restrict__ src3,
    uint32_t sb, float (&acc)[4][8][4])
{
    const int tid  = threadIdx.x;
    const int lane = tid & 31;
    const int wid  = tid >> 5;           // 0..3
    const int warpM = wid & 1;
    const int warpN = wid >> 1;          // 0..1
    const int l16 = lane & 15, lh2 = lane >> 4;
    const int bkey = (lane & 7) | ((lane >> 4) << 3);
    const int bch  = (lane >> 3) & 1;

    const __nv_bfloat16* srcs[4] = {src0, src1, src2, src3};

#pragma unroll
    for (int mi = 0; mi < 4; mi++)
#pragma unroll
        for (int ni = 0; ni < 8; ni++)
#pragma unroll
            for (int j = 0; j < 4; j++) acc[mi][ni][j] = 0.f;

    auto load_stage = [&](int kt, int slot) {
        const int k0 = kt * KSTG;
        uint32_t base = sb + (uint32_t)slot * SWORDS * 4;
#pragma unroll
        for (int t = 0; t < 4; t++) {
            const __nv_bfloat16* src = srcs[t] + k0;
            uint32_t db = base + (uint32_t)t * TWORDS * 4;
#pragma unroll
            for (int q = 0; q < 4; q++) {
                int idx = tid + q * GEMM_THREADS;   // 0..511
                int r = idx >> 2;                    // row 0..127
                int c = idx & 3;                     // 16B chunk 0..3
                int pos = (c ^ ((r >> 1) & 3)) & 3;
                cp16(db + (uint32_t)(r * 16 + pos * 4) * 4,
                     src + (size_t)r * DD + c * 8);
            }
        }
    };

    load_stage(0, 0); CP_COMMIT();
    load_stage(1, 1); CP_COMMIT();

    int aR[4], aS[4];
#pragma unroll
    for (int mi = 0; mi < 4; mi++) {
        aR[mi] = warpM * 64 + mi * 16 + l16;
        aS[mi] = (aR[mi] >> 1) & 3;
    }
    int bR[4], bS[4];
#pragma unroll
    for (int jj = 0; jj < 4; jj++) {
        bR[jj] = warpN * 64 + jj * 16 + bkey;
        bS[jj] = (bR[jj] >> 1) & 3;
    }

    int slot = 0;
    for (int kt = 0; kt < NSTG; kt++) {
        CP_WAIT(1);          // load(kt) landed
        __syncthreads();     // ring slot reuse safe
        if (kt + 2 < NSTG) {
            int s2 = slot - 1; if (s2 < 0) s2 = 2;   // (kt+2) % 3
            load_stage(kt + 2, s2);
        }
        CP_COMMIT();         // one group per stage keeps wait algebra fixed

        uint32_t tb = sb + (uint32_t)slot * SWORDS * 4;
        uint32_t pAh = tb;
        uint32_t pAl = tb + TWORDS * 4;
        uint32_t pBh = tb + 2 * TWORDS * 4;
        uint32_t pBl = tb + 3 * TWORDS * 4;

#pragma unroll
        for (int ks = 0; ks < 2; ks++) {
            uint32_t ah[4][4], al[4][4], bf[8][2];
            int ja = ks * 2 + lh2;
#pragma unroll
            for (int mi = 0; mi < 4; mi++) {
                uint32_t wo = (uint32_t)(aR[mi] * 16 + ((ja ^ aS[mi]) & 3) * 4) * 4;
                ldsm_x4(ah[mi], pAh + wo);
                ldsm_x4(al[mi], pAl + wo);
            }
            int jb = ks * 2 + bch;
            // B-hi plane: ah*bh + al*bh
#pragma unroll
            for (int jj = 0; jj < 4; jj++) {
                uint32_t wo = (uint32_t)(bR[jj] * 16 + ((jb ^ bS[jj]) & 3) * 4) * 4;
                uint32_t r[4];
                ldsm_x4(r, pBh + wo);
                bf[2*jj][0] = r[0]; bf[2*jj][1] = r[1];
                bf[2*jj+1][0] = r[2]; bf[2*jj+1][1] = r[3];
            }
#pragma unroll
            for (int mi = 0; mi < 4; mi++)
#pragma unroll
                for (int ni = 0; ni < 8; ni++) {
                    mma16816(acc[mi][ni], ah[mi], bf[ni]);
                    mma16816(acc[mi][ni], al[mi], bf[ni]);
                }
            // B-lo plane: ah*bl
#pragma unroll
            for (int jj = 0; jj < 4; jj++) {
                uint32_t wo = (uint32_t)(bR[jj] * 16 + ((jb ^ bS[jj]) & 3) * 4) * 4;
                uint32_t r[4];
                ldsm_x4(r, pBl + wo);
                bf[2*jj][0] = r[0]; bf[2*jj][1] = r[1];
                bf[2*jj+1][0] = r[2]; bf[2*jj+1][1] = r[3];
            }
#pragma unroll
            for (int mi = 0; mi < 4; mi++)
#pragma unroll
                for (int ni = 0; ni < 8; ni++)
                    mma16816(acc[mi][ni], ah[mi], bf[ni]);
        }
        slot = (slot == 2) ? 0 : slot + 1;
    }
}

// ---------------- fused QKV projection (z = 0:Q, 1:K, 2:V) -------------------
__global__ void __launch_bounds__(GEMM_THREADS, 2) gemm_qkv_kernel(
    const __nv_bfloat16* __restrict__ Xh, const __nv_bfloat16* __restrict__ Xl,
    const __nv_bfloat16* __restrict__ Wh, const __nv_bfloat16* __restrict__ Wl,
    __nv_bfloat16* __restrict__ Qh, __nv_bfloat16* __restrict__ Ql,
    __nv_bfloat16* __restrict__ Kh, __nv_bfloat16* __restrict__ Kl,
    __nv_bfloat16* __restrict__ Vh, __nv_bfloat16* __restrict__ Vl)
{
    extern __shared__ uint32_t sm4[];
    uint32_t sb = smem_u32(sm4);
    const int z = blockIdx.z;
    const int row0 = blockIdx.y * 128;
    const int col0 = blockIdx.x * 128;
    const __nv_bfloat16* Bh = Wh + (size_t)z * DD * DD + (size_t)col0 * DD;
    const __nv_bfloat16* Bl = Wl + (size_t)z * DD * DD + (size_t)col0 * DD;

    float acc[4][8][4];
    gemm_core(Xh + (size_t)row0 * DD, Xl + (size_t)row0 * DD, Bh, Bl, sb, acc);

    __nv_bfloat16* Oh = (z == 0) ? Qh : (z == 1) ? Kh : Vh;
    __nv_bfloat16* Ol = (z == 0) ? Ql : (z == 1) ? Kl : Vl;
    const bool dorope = (z < 2);

    const int lane = threadIdx.x & 31, wid = threadIdx.x >> 5;
    const int warpM = wid & 1, warpN = wid >> 1;
    const int g = lane >> 2, t4 = lane & 3;
    const int h = blockIdx.x;

#pragma unroll
    for (int mi = 0; mi < 4; mi++) {
#pragma unroll
        for (int ni = 0; ni < 8; ni++) {
            int m0 = row0 + warpM * 64 + mi * 16 + g;
            int d  = warpN * 64 + ni * 8 + t4 * 2;
            float v0 = acc[mi][ni][0], v1 = acc[mi][ni][1];
            float v2 = acc[mi][ni][2], v3 = acc[mi][ni][3];
            int b0i = m0 >> 11, s0 = m0 & 2047;
            int b1i = (m0 + 8) >> 11, s1 = (m0 + 8) & 2047;
            if (dorope) {
                int p = d >> 1;
                float c0 = g_cos[s0 * 64 + p], sn0 = g_sin[s0 * 64 + p];
                float c1 = g_cos[s1 * 64 + p], sn1 = g_sin[s1 * 64 + p];
                float r0 = v0 * c0 - v1 * sn0, r1 = v0 * sn0 + v1 * c0;
                float r2 = v2 * c1 - v3 * sn1, r3 = v2 * sn1 + v3 * c1;
                v0 = r0; v1 = r1; v2 = r2; v3 = r3;
            }
            size_t i0 = ((size_t)(b0i * HH + h) * SS + s0) * HD + d;
            size_t i1 = ((size_t)(b1i * HH + h) * SS + s1) * HD + d;
            uint32_t hp, lp;
            split2(v0, v1, hp, lp);
            *(uint32_t*)&Oh[i0] = hp;
            *(uint32_t*)&Ol[i0] = lp;
            split2(v2, v3, hp, lp);
            *(uint32_t*)&Oh[i1] = hp;
            *(uint32_t*)&Ol[i1] = lp;
        }
    }
}

// ---------------- output projection + bias -----------------------------------
__global__ void __launch_bounds__(GEMM_THREADS, 2) gemm_o_kernel(
    const __nv_bfloat16* __restrict__ Ah, const __nv_bfloat16* __restrict__ Al,
    const __nv_bfloat16* __restrict__ Bh, const __nv_bfloat16* __restrict__ Bl,
    const float* __restrict__ bias, float* __restrict__ C)
{
    extern __shared__ uint32_t sm4[];
    uint32_t sb = smem_u32(sm4);
    const int row0 = blockIdx.y * 128;
    const int col0 = blockIdx.x * 128;

    float acc[4][8][4];
    gemm_core(Ah + (size_t)row0 * DD, Al + (size_t)row0 * DD,
              Bh + (size_t)col0 * DD, Bl + (size_t)col0 * DD, sb, acc);

    const int lane = threadIdx.x & 31, wid = threadIdx.x >> 5;
    const int warpM = wid & 1, warpN = wid >> 1;
    const int g = lane >> 2, t4 = lane & 3;

#pragma unroll
    for (int mi = 0; mi < 4; mi++) {
#pragma unroll
        for (int ni = 0; ni < 8; ni++) {
            int m0 = row0 + warpM * 64 + mi * 16 + g;
            int n  = col0 + warpN * 64 + ni * 8 + t4 * 2;
            float b0 = bias[n], b1 = bias[n + 1];
            *(float2*)&C[(size_t)m0 * DD + n] =
                make_float2(acc[mi][ni][0] + b0, acc[mi][ni][1] + b1);
            *(float2*)&C[(size_t)(m0 + 8) * DD + n] =
                make_float2(acc[mi][ni][2] + b0, acc[mi][ni][3] + b1);
        }
    }
}

// ---------------- HMMA flash attention, single-sync pipeline (R12) -----------
#define AT_QH 0
#define AT_QL 9216
#define AT_KV 18432
#define AT_STG 18432
#define ATT_SMEM (55296*4)   // 221184 B

__global__ void __launch_bounds__(256, 1) attn_mma_kernel(
    const __nv_bfloat16* __restrict__ Qh, const __nv_bfloat16* __restrict__ Ql,
    const __nv_bfloat16* __restrict__ Kh, const __nv_bfloat16* __restrict__ Kl,
    const __nv_bfloat16* __restrict__ Vh, const __nv_bfloat16* __restrict__ Vl,
    __nv_bfloat16* __restrict__ CH, __nv_bfloat16* __restrict__ CL)
{
    extern __shared__ uint32_t smw[];
    uint32_t sb = smem_u32(smw);
    const int tid = threadIdx.x, lane = tid & 31, w = tid >> 5;
    const int g = lane >> 2, t4 = lane & 3;
    const int bh = blockIdx.y;
    const int bidx = bh / HH, hidx = bh % HH;
    const int qb = gridDim.x - 1 - blockIdx.x;
    const int q0 = qb * 128;
    const int nkt = qb * 2 + 2;
    const size_t hb = (size_t)bh * SS * HD;

    const int l16 = lane & 15, lh2 = lane >> 4;
    const int bkey = (lane & 7) | ((lane >> 4) << 3);
    const int bch  = (lane >> 3) & 1;
    const int vkey = (lane & 7) | (((lane >> 3) & 1) << 3);
    const int vch  = lane >> 4;

    {
        const __nv_bfloat16* qs0 = Qh + hb + (size_t)q0 * HD;
        const __nv_bfloat16* qs1 = Ql + hb + (size_t)q0 * HD;
#pragma unroll
        for (int i = 0; i < 16; i++) {
            int idx = tid + i * 256;
            int pl = idx >> 11;
            int c = idx & 2047;
            int row = c >> 4;
            int piece = c & 15;
            uint32_t dw = (pl ? AT_QL : AT_QH) + (piece >> 3) * 4608
                        + row * 36 + (piece & 7) * 4;
            cp16(sb + dw * 4, (pl ? qs1 : qs0) + (size_t)row * HD + piece * 8);
        }
    }
    const __nv_bfloat16* kvsrc[4] = {Kh + hb, Kl + hb, Vh + hb, Vl + hb};
    auto load_k = [&](int kt, int buf) {
        int k0 = kt * 64;
#pragma unroll
        for (int i = 0; i < 8; i++) {
            int idx = tid + i * 256;
            int pl = idx >> 10;
            int c = idx & 1023;
            int row = c >> 4;
            int piece = c & 15;
            uint32_t dw = AT_KV + buf * AT_STG + pl * 4608 + (piece >> 3) * 2304
                        + row * 36 + (piece & 7) * 4;
            cp16(sb + dw * 4, kvsrc[pl] + (size_t)(k0 + row) * HD + piece * 8);
        }
    };
    auto load_v = [&](int kt, int buf) {
        int k0 = kt * 64;
#pragma unroll
        for (int i = 0; i < 8; i++) {
            int idx = tid + i * 256;
            int pl = idx >> 10;
            int c = idx & 1023;
            int row = c >> 4;
            int piece = c & 15;
            uint32_t dw = AT_KV + buf * AT_STG + (2 + pl) * 4608 + (piece >> 3) * 2304
                        + row * 36 + (piece & 7) * 4;
            cp16(sb + dw * 4, kvsrc[2 + pl] + (size_t)(k0 + row) * HD + piece * 8);
        }
    };

    float ofr[16][4];
#pragma unroll
    for (int i = 0; i < 16; i++)
#pragma unroll
        for (int j = 0; j < 4; j++) ofr[i][j] = 0.f;
    float m0 = -1e30f, m1 = -1e30f, l0 = 0.f, l1 = 0.f;
    const float scale = 0.08838834764831845f;
    const uint32_t qwoff = (uint32_t)(w * 16 + l16) * 36;
    const int rowg = q0 + w * 16 + g;

    float sf[8][4];

    auto qk_into = [&](int buf) {
        uint32_t stg = AT_KV + (uint32_t)buf * AT_STG;
#pragma unroll
        for (int n = 0; n < 8; n++)
#pragma unroll
            for (int c = 0; c < 4; c++) sf[n][c] = 0.f;
#pragma unroll
        for (int ks = 0; ks < 8; ks++) {
            uint32_t qwo = ((uint32_t)(ks >> 2) * 4608 + qwoff + (ks & 3) * 8 + lh2 * 4) * 4;
            uint32_t qh4[4], ql4[4];
            ldsm_x4(qh4, sb + AT_QH * 4 + qwo);
            ldsm_x4(ql4, sb + AT_QL * 4 + qwo);
            uint32_t khf[8][2], klf[8][2];
#pragma unroll
            for (int j = 0; j < 4; j++) {
                uint32_t kwo = (stg + (uint32_t)(ks >> 2) * 2304
                              + (uint32_t)(j * 16 + bkey) * 36 + (ks & 3) * 8 + bch * 4) * 4;
                uint32_t r[4];
                ldsm_x4(r, sb + kwo);
                khf[2*j][0] = r[0]; khf[2*j][1] = r[1];
                khf[2*j+1][0] = r[2]; khf[2*j+1][1] = r[3];
                ldsm_x4(r, sb + kwo + 4608 * 4);
                klf[2*j][0] = r[0]; klf[2*j][1] = r[1];
                klf[2*j+1][0] = r[2]; klf[2*j+1][1] = r[3];
            }
#pragma unroll
            for (int n = 0; n < 8; n++) {
                mma16816(sf[n], qh4, khf[n]);
                mma16816(sf[n], qh4, klf[n]);
                mma16816(sf[n], ql4, khf[n]);
            }
        }
    };

    load_k(0, 0); load_v(0, 0); CP_COMMIT();
    load_k(1, 1); CP_COMMIT();
    CP_WAIT(0);
    __syncthreads();
    qk_into(0);

    for (int t = 0; t < nkt; t++) {
        const int buf = t & 1;
        CP_WAIT(0);
        __syncthreads();
        if (t + 2 < nkt) load_k(t + 2, buf);
        if (t + 1 < nkt) load_v(t + 1, buf ^ 1);
        CP_COMMIT();

        const bool act = !(t == nkt - 1 && w < 4);
        const bool actnext = (t + 1 < nkt) && !((t + 1) == nkt - 1 && w < 4);

        uint32_t ph[4][4], plo[4][4];
        if (act) {
            int k0 = t * 64;
            bool domask = (t >= nkt - 2);
            float mx0 = -1e30f, mx1 = -1e30f;
#pragma unroll
            for (int n = 0; n < 8; n++) {
#pragma unroll
                for (int c = 0; c < 4; c++) {
                    float v = sf[n][c] * scale;
                    if (domask) {
                        int col = k0 + n * 8 + 2 * t4 + (c & 1);
                        int row = rowg + ((c >> 1) << 3);
                        if (col > row) v = -1e30f;
                    }
                    sf[n][c] = v;
                    if (c < 2) mx0 = fmaxf(mx0, v); else mx1 = fmaxf(mx1, v);
                }
            }
            mx0 = fmaxf(mx0, __shfl_xor_sync(0xffffffffu, mx0, 1));
            mx0 = fmaxf(mx0, __shfl_xor_sync(0xffffffffu, mx0, 2));
            mx1 = fmaxf(mx1, __shfl_xor_sync(0xffffffffu, mx1, 1));
            mx1 = fmaxf(mx1, __shfl_xor_sync(0xffffffffu, mx1, 2));
            float mn0 = fmaxf(m0, mx0), mn1 = fmaxf(m1, mx1);
            float a0 = fexp(m0 - mn0), a1 = fexp(m1 - mn1);
            m0 = mn0; m1 = mn1;
            float s0 = 0.f, s1 = 0.f;
#pragma unroll
            for (int n = 0; n < 8; n++) {
                sf[n][0] = fexp(sf[n][0] - mn0); s0 += sf[n][0];
                sf[n][1] = fexp(sf[n][1] - mn0); s0 += sf[n][1];
                sf[n][2] = fexp(sf[n][2] - mn1); s1 += sf[n][2];
                sf[n][3] = fexp(sf[n][3] - mn1); s1 += sf[n][3];
            }
            s0 += __shfl_xor_sync(0xffffffffu, s0, 1);
            s0 += __shfl_xor_sync(0xffffffffu, s0, 2);
            s1 += __shfl_xor_sync(0xffffffffu, s1, 1);
            s1 += __shfl_xor_sync(0xffffffffu, s1, 2);
            l0 = l0 * a0 + s0;
            l1 = l1 * a1 + s1;
#pragma unroll
            for (int nc = 0; nc < 16; nc++) {
                ofr[nc][0] *= a0; ofr[nc][1] *= a0;
                ofr[nc][2] *= a1; ofr[nc][3] *= a1;
            }
#pragma unroll
            for (int kb = 0; kb < 4; kb++) {
                split2(sf[2*kb][0],   sf[2*kb][1],   ph[kb][0], plo[kb][0]);
                split2(sf[2*kb][2],   sf[2*kb][3],   ph[kb][1], plo[kb][1]);
                split2(sf[2*kb+1][0], sf[2*kb+1][1], ph[kb][2], plo[kb][2]);
                split2(sf[2*kb+1][2], sf[2*kb+1][3], ph[kb][3], plo[kb][3]);
            }
        }

        if (actnext) qk_into(buf ^ 1);

        if (act) {
            uint32_t stg = AT_KV + (uint32_t)buf * AT_STG;
#pragma unroll
            for (int kb = 0; kb < 4; kb++) {
                uint32_t krow = (uint32_t)(kb * 16 + vkey) * 36;
#pragma unroll
                for (int jj = 0; jj < 8; jj++) {
                    int cj = jj * 2 + vch;
                    uint32_t vwo = (stg + 9216u + (uint32_t)(cj >> 3) * 2304
                                  + krow + (uint32_t)(cj & 7) * 4) * 4;
                    uint32_t rv[4], rl[4];
                    ldsm_x4_t(rv, sb + vwo);
                    ldsm_x4_t(rl, sb + vwo + 4608 * 4);
                    mma2(ofr[2*jj],   ph[kb], rv[0], rv[1]);
                    mma2(ofr[2*jj],   ph[kb], rl[0], rl[1]);
                    mma2(ofr[2*jj],   plo[kb], rv[0], rv[1]);
                    mma2(ofr[2*jj+1], ph[kb], rv[2], rv[3]);
                    mma2(ofr[2*jj+1], ph[kb], rl[2], rl[3]);
                    mma2(ofr[2*jj+1], plo[kb], rv[2], rv[3]);
                }
            }
        }
    }

    float i0 = 1.f / l0, i1 = 1.f / l1;
    int r0 = q0 + w * 16 + g, r1 = r0 + 8;
    size_t base0 = ((size_t)(bidx * SS + r0)) * DD + hidx * HD;
    size_t base1 = ((size_t)(bidx * SS + r1)) * DD + hidx * HD;
#pragma unroll
    for (int nc = 0; nc < 16; nc++) {
        int d = nc * 8 + 2 * t4;
        uint32_t hp, lp;
        split2(ofr[nc][0] * i0, ofr[nc][1] * i0, hp, lp);
        *(uint32_t*)&CH[base0 + d] = hp;
        *(uint32_t*)&CL[base0 + d] = lp;
        split2(ofr[nc][2] * i1, ofr[nc][3] * i1, hp, lp);
        *(uint32_t*)&CH[base1 + d] = hp;
        *(uint32_t*)&CL[base1 + d] = lp;
    }
}

// ---------------------------------------------------------------------------
extern "C" void kernel_launch(void* const* d_in, const int* in_sizes, int n_in,
                              void* d_out, int out_size)
{
    const float* x  = (const float*)d_in[0];
    const float* wq = (const float*)d_in[1];
    const float* wk = (const float*)d_in[2];
    const float* wv = (const float*)d_in[3];
    const float* wo = (const float*)d_in[4];
    const float* bo = (const float*)d_in[5];
    float* out = (float*)d_out;

    __nv_bfloat16 *qh, *ql, *kh, *kl, *vh, *vl, *xh, *xl, *wh, *wl, *ch, *cl;
    cudaGetSymbolAddress((void**)&qh, g_qh);
    cudaGetSymbolAddress((void**)&ql, g_ql);
    cudaGetSymbolAddress((void**)&kh, g_kh);
    cudaGetSymbolAddress((void**)&kl, g_kl);
    cudaGetSymbolAddress((void**)&vh, g_vh);
    cudaGetSymbolAddress((void**)&vl, g_vl);
    cudaGetSymbolAddress((void**)&xh, g_xh);
    cudaGetSymbolAddress((void**)&xl, g_xl);
    cudaGetSymbolAddress((void**)&wh, g_wh);
    cudaGetSymbolAddress((void**)&wl, g_wl);
    cudaGetSymbolAddress((void**)&ch, g_ch);
    cudaGetSymbolAddress((void**)&cl, g_cl);

    cudaFuncSetAttribute(gemm_qkv_kernel, cudaFuncAttributeMaxDynamicSharedMemorySize, GEMM_SMEM);
    cudaFuncSetAttribute(gemm_o_kernel,   cudaFuncAttributeMaxDynamicSharedMemorySize, GEMM_SMEM);
    cudaFuncSetAttribute(attn_mma_kernel, cudaFuncAttributeMaxDynamicSharedMemorySize, ATT_SMEM);

    // launch order: gemm_o is the 4th launch -> lands in the ncu capture slot
    cvt_all_kernel<<<(CVT_TOTAL + 255) / 256, 256>>>(                         // 1
        x, wq, wk, wv, wo, xh, xl, wh, wl);

    gemm_qkv_kernel<<<dim3(DD / 128, MM / 128, 3), GEMM_THREADS, GEMM_SMEM>>>(// 2
        xh, xl, wh, wl, qh, ql, kh, kl, vh, vl);

    attn_mma_kernel<<<dim3(SS / 128, BB * HH), 256, ATT_SMEM>>>(              // 3
        qh, ql, kh, kl, vh, vl, ch, cl);

    gemm_o_kernel<<<dim3(DD / 128, MM / 128), GEMM_THREADS, GEMM_SMEM>>>(     // 4
        ch, cl, wh + (size_t)3 * DD * DD, wl + (size_t)3 * DD * DD, bo, out);
}

// round 16
// speedup vs baseline: 1.0003x; 1.0003x over previous
#include <cuda_runtime.h>
#include <cuda_bf16.h>
#include <math.h>
#include <stdint.h>

#define BB 4
#define SS 2048
#define DD 2048
#define HH 16
#define HD 128
#define MM (BB*SS)   // 8192

// ---------------- scratch (device globals: allocation-free rule) -----------
__device__ __nv_bfloat16 g_qh[(size_t)BB*HH*SS*HD];
__device__ __nv_bfloat16 g_ql[(size_t)BB*HH*SS*HD];
__device__ __nv_bfloat16 g_kh[(size_t)BB*HH*SS*HD];
__device__ __nv_bfloat16 g_kl[(size_t)BB*HH*SS*HD];
__device__ __nv_bfloat16 g_vh[(size_t)BB*HH*SS*HD];
__device__ __nv_bfloat16 g_vl[(size_t)BB*HH*SS*HD];
__device__ __nv_bfloat16 g_xh[(size_t)MM*DD];
__device__ __nv_bfloat16 g_xl[(size_t)MM*DD];
__device__ __nv_bfloat16 g_wh[(size_t)4*DD*DD];
__device__ __nv_bfloat16 g_wl[(size_t)4*DD*DD];
__device__ __nv_bfloat16 g_ch[(size_t)MM*DD];
__device__ __nv_bfloat16 g_cl[(size_t)MM*DD];
__device__ float g_cos[SS*64];
__device__ float g_sin[SS*64];

// ---------------- helpers ----------------------------------------------------
__device__ __forceinline__ uint32_t smem_u32(const void* p) {
    uint32_t a;
    asm("{ .reg .u64 t; cvta.to.shared.u64 t, %1; cvt.u32.u64 %0, t; }"
        : "=r"(a) : "l"(p));
    return a;
}
__device__ __forceinline__ void cp16(uint32_t dst, const void* src) {
    asm volatile("cp.async.cg.shared.global [%0], [%1], 16;" :: "r"(dst), "l"(src));
}
#define CP_COMMIT() asm volatile("cp.async.commit_group;" ::: "memory")
#define CP_WAIT(n)  asm volatile("cp.async.wait_group %0;" :: "n"(n) : "memory")

__device__ __forceinline__ void mma16816(float* c, const uint32_t* a, const uint32_t* b) {
    asm volatile(
        "mma.sync.aligned.m16n8k16.row.col.f32.bf16.bf16.f32 "
        "{%0,%1,%2,%3}, {%4,%5,%6,%7}, {%8,%9}, {%0,%1,%2,%3};"
        : "+f"(c[0]), "+f"(c[1]), "+f"(c[2]), "+f"(c[3])
        : "r"(a[0]), "r"(a[1]), "r"(a[2]), "r"(a[3]), "r"(b[0]), "r"(b[1]));
}
__device__ __forceinline__ void mma2(float* c, const uint32_t* a, uint32_t b0, uint32_t b1) {
    asm volatile(
        "mma.sync.aligned.m16n8k16.row.col.f32.bf16.bf16.f32 "
        "{%0,%1,%2,%3}, {%4,%5,%6,%7}, {%8,%9}, {%0,%1,%2,%3};"
        : "+f"(c[0]), "+f"(c[1]), "+f"(c[2]), "+f"(c[3])
        : "r"(a[0]), "r"(a[1]), "r"(a[2]), "r"(a[3]), "r"(b0), "r"(b1));
}
__device__ __forceinline__ void ldsm_x4(uint32_t* r, uint32_t addr) {
    asm volatile("ldmatrix.sync.aligned.m8n8.x4.shared.b16 {%0,%1,%2,%3}, [%4];"
        : "=r"(r[0]), "=r"(r[1]), "=r"(r[2]), "=r"(r[3]) : "r"(addr));
}
__device__ __forceinline__ void ldsm_x4_t(uint32_t* r, uint32_t addr) {
    asm volatile("ldmatrix.sync.aligned.m8n8.x4.trans.shared.b16 {%0,%1,%2,%3}, [%4];"
        : "=r"(r[0]), "=r"(r[1]), "=r"(r[2]), "=r"(r[3]) : "r"(addr));
}
__device__ __forceinline__ uint32_t packbf(float lo, float hi) {
    uint32_t r;
    asm("cvt.rn.bf16x2.f32 %0, %1, %2;" : "=r"(r) : "f"(hi), "f"(lo));
    return r;
}
__device__ __forceinline__ void split2(float x, float y, uint32_t& hp, uint32_t& lp) {
    hp = packbf(x, y);
    float hx = __int_as_float(hp << 16);
    float hy = __int_as_float(hp & 0xFFFF0000u);
    lp = packbf(x - hx, y - hy);
}
// fast exp on FMA/ALU pipes (x <= ~0), rel err ~2e-6
__device__ __forceinline__ float fexp(float x) {
    float y = fmaxf(x * 1.4426950408889634f, -120.f);
    float t = y + 12582912.f;
    int n = __float_as_int(t) - 0x4B400000;
    float f = y - (t - 12582912.f);
    float p = 1.3333558146e-3f;
    p = fmaf(p, f, 9.6181291076e-3f);
    p = fmaf(p, f, 5.5504108665e-2f);
    p = fmaf(p, f, 2.4022650696e-1f);
    p = fmaf(p, f, 6.9314718056e-1f);
    p = fmaf(p, f, 1.0f);
    return p * __int_as_float((127 + n) << 23);
}

// ---------------- unified conversion kernel (x, 4 weights, rope) -------------
// 8 floats per thread -> 16B stores on all four output streams
__device__ __forceinline__ void split8(const float* in, __nv_bfloat16* hi,
                                       __nv_bfloat16* lo, int i) {
    float4 v0 = ((const float4*)in)[2 * i];
    float4 v1 = ((const float4*)in)[2 * i + 1];
    float a[8] = {v0.x, v0.y, v0.z, v0.w, v1.x, v1.y, v1.z, v1.w};
    __align__(16) __nv_bfloat16 h[8], l[8];
#pragma unroll
    for (int j = 0; j < 8; j++) {
        h[j] = __float2bfloat16(a[j]);
        l[j] = __float2bfloat16(a[j] - __bfloat162float(h[j]));
    }
    *(uint4*)&hi[(size_t)i * 8] = *(uint4*)h;
    *(uint4*)&lo[(size_t)i * 8] = *(uint4*)l;
}

#define XN8 (MM*DD/8)     // 2097152
#define WN8 (DD*DD/8)     // 524288 = 2^19
#define CVT_TOTAL (XN8 + 4*WN8 + SS*64)

__global__ void cvt_all_kernel(const float* __restrict__ x,
                               const float* __restrict__ wq, const float* __restrict__ wk,
                               const float* __restrict__ wv, const float* __restrict__ wo,
                               __nv_bfloat16* __restrict__ xh, __nv_bfloat16* __restrict__ xl,
                               __nv_bfloat16* __restrict__ wh, __nv_bfloat16* __restrict__ wl)
{
    int i = blockIdx.x * blockDim.x + threadIdx.x;
    if (i < XN8) { split8(x, xh, xl, i); return; }
    i -= XN8;
    if (i < 4 * WN8) {
        int wsel = i >> 19;
        int j = i & (WN8 - 1);
        const float* w = (wsel == 0) ? wq : (wsel == 1) ? wk : (wsel == 2) ? wv : wo;
        split8(w, wh + (size_t)wsel * DD * DD, wl + (size_t)wsel * DD * DD, j);
        return;
    }
    i -= 4 * WN8;
    if (i < SS * 64) {
        int s = i >> 6, p = i & 63;
        double invf = exp(-(double)p * (log(10000.0) / 64.0));
        float ang = (float)s * (float)invf;
        float sv, cv;
        sincosf(ang, &sv, &cv);
        g_cos[i] = cv;
        g_sin[i] = sv;
    }
}

// ---------------- shared GEMM mainloop (R12: 64x64 warp tile, two-phase B) ----
#define KSTG    32
#define TWORDS  2048                 // 128 rows * 16 words
#define SWORDS  (4*TWORDS)           // 8192 words = 32 KB per stage
#define GEMM_SMEM (3*SWORDS*4)       // 98304 bytes -> 2 CTAs/SM
#define NSTG    (DD/KSTG)            // 64
#define GEMM_THREADS 128

__device__ __forceinline__ void gemm_core(
    const __nv_bfloat16* __restrict__ src0, const __nv_bfloat16* __restrict__ src1,
    const __nv_bfloat16* __restrict__ src2, const __nv_bfloat16* __restrict__ src3,
    uint32_t sb, float (&acc)[4][8][4])
{
    const int tid  = threadIdx.x;
    const int lane = tid & 31;
    const int wid  = tid >> 5;           // 0..3
    const int warpM = wid & 1;
    const int warpN = wid >> 1;          // 0..1
    const int l16 = lane & 15, lh2 = lane >> 4;
    const int bkey = (lane & 7) | ((lane >> 4) << 3);
    const int bch  = (lane >> 3) & 1;

    const __nv_bfloat16* srcs[4] = {src0, src1, src2, src3};

#pragma unroll
    for (int mi = 0; mi < 4; mi++)
#pragma unroll
        for (int ni = 0; ni < 8; ni++)
#pragma unroll
            for (int j = 0; j < 4; j++) acc[mi][ni][j] = 0.f;

    auto load_stage = [&](int kt, int slot) {
        const int k0 = kt * KSTG;
        uint32_t base = sb + (uint32_t)slot * SWORDS * 4;
#pragma unroll
        for (int t = 0; t < 4; t++) {
            const __nv_bfloat16* src = srcs[t] + k0;
            uint32_t db = base + (uint32_t)t * TWORDS * 4;
#pragma unroll
            for (int q = 0; q < 4; q++) {
                int idx = tid + q * GEMM_THREADS;   // 0..511
                int r = idx >> 2;                    // row 0..127
                int c = idx & 3;                     // 16B chunk 0..3
                int pos = (c ^ ((r >> 1) & 3)) & 3;
                cp16(db + (uint32_t)(r * 16 + pos * 4) * 4,
                     src + (size_t)r * DD + c * 8);
            }
        }
    };

    load_stage(0, 0); CP_COMMIT();
    load_stage(1, 1); CP_COMMIT();

    int aR[4], aS[4];
#pragma unroll
    for (int mi = 0; mi < 4; mi++) {
        aR[mi] = warpM * 64 + mi * 16 + l16;
        aS[mi] = (aR[mi] >> 1) & 3;
    }
    int bR[4], bS[4];
#pragma unroll
    for (int jj = 0; jj < 4; jj++) {
        bR[jj] = warpN * 64 + jj * 16 + bkey;
        bS[jj] = (bR[jj] >> 1) & 3;
    }

    int slot = 0;
    for (int kt = 0; kt < NSTG; kt++) {
        CP_WAIT(1);          // load(kt) landed
        __syncthreads();     // ring slot reuse safe
        if (kt + 2 < NSTG) {
            int s2 = slot - 1; if (s2 < 0) s2 = 2;   // (kt+2) % 3
            load_stage(kt + 2, s2);
        }
        CP_COMMIT();         // one group per stage keeps wait algebra fixed

        uint32_t tb = sb + (uint32_t)slot * SWORDS * 4;
        uint32_t pAh = tb;
        uint32_t pAl = tb + TWORDS * 4;
        uint32_t pBh = tb + 2 * TWORDS * 4;
        uint32_t pBl = tb + 3 * TWORDS * 4;

#pragma unroll
        for (int ks = 0; ks < 2; ks++) {
            uint32_t ah[4][4], al[4][4], bf[8][2];
            int ja = ks * 2 + lh2;
#pragma unroll
            for (int mi = 0; mi < 4; mi++) {
                uint32_t wo = (uint32_t)(aR[mi] * 16 + ((ja ^ aS[mi]) & 3) * 4) * 4;
                ldsm_x4(ah[mi], pAh + wo);
                ldsm_x4(al[mi], pAl + wo);
            }
            int jb = ks * 2 + bch;
            // B-hi plane: ah*bh + al*bh
#pragma unroll
            for (int jj = 0; jj < 4; jj++) {
                uint32_t wo = (uint32_t)(bR[jj] * 16 + ((jb ^ bS[jj]) & 3) * 4) * 4;
                uint32_t r[4];
                ldsm_x4(r, pBh + wo);
                bf[2*jj][0] = r[0]; bf[2*jj][1] = r[1];
                bf[2*jj+1][0] = r[2]; bf[2*jj+1][1] = r[3];
            }
#pragma unroll
            for (int mi = 0; mi < 4; mi++)
#pragma unroll
                for (int ni = 0; ni < 8; ni++) {
                    mma16816(acc[mi][ni], ah[mi], bf[ni]);
                    mma16816(acc[mi][ni], al[mi], bf[ni]);
                }
            // B-lo plane: ah*bl
#pragma unroll
            for (int jj = 0; jj < 4; jj++) {
                uint32_t wo = (uint32_t)(bR[jj] * 16 + ((jb ^ bS[jj]) & 3) * 4) * 4;
                uint32_t r[4];
                ldsm_x4(r, pBl + wo);
                bf[2*jj][0] = r[0]; bf[2*jj][1] = r[1];
                bf[2*jj+1][0] = r[2]; bf[2*jj+1][1] = r[3];
            }
#pragma unroll
            for (int mi = 0; mi < 4; mi++)
#pragma unroll
                for (int ni = 0; ni < 8; ni++)
                    mma16816(acc[mi][ni], ah[mi], bf[ni]);
        }
        slot = (slot == 2) ? 0 : slot + 1;
    }
}

// ---------------- fused QKV projection (z = 0:Q, 1:K, 2:V) -------------------
__global__ void __launch_bounds__(GEMM_THREADS, 2) gemm_qkv_kernel(
    const __nv_bfloat16* __restrict__ Xh, const __nv_bfloat16* __restrict__ Xl,
    const __nv_bfloat16* __restrict__ Wh, const __nv_bfloat16* __restrict__ Wl,
    __nv_bfloat16* __restrict__ Qh, __nv_bfloat16* __restrict__ Ql,
    __nv_bfloat16* __restrict__ Kh, __nv_bfloat16* __restrict__ Kl,
    __nv_bfloat16* __restrict__ Vh, __nv_bfloat16* __restrict__ Vl)
{
    extern __shared__ uint32_t sm4[];
    uint32_t sb = smem_u32(sm4);
    const int z = blockIdx.z;
    const int row0 = blockIdx.y * 128;
    const int col0 = blockIdx.x * 128;
    const __nv_bfloat16* Bh = Wh + (size_t)z * DD * DD + (size_t)col0 * DD;
    const __nv_bfloat16* Bl = Wl + (size_t)z * DD * DD + (size_t)col0 * DD;

    float acc[4][8][4];
    gemm_core(Xh + (size_t)row0 * DD, Xl + (size_t)row0 * DD, Bh, Bl, sb, acc);

    __nv_bfloat16* Oh = (z == 0) ? Qh : (z == 1) ? Kh : Vh;
    __nv_bfloat16* Ol = (z == 0) ? Ql : (z == 1) ? Kl : Vl;
    const bool dorope = (z < 2);

    const int lane = threadIdx.x & 31, wid = threadIdx.x >> 5;
    const int warpM = wid & 1, warpN = wid >> 1;
    const int g = lane >> 2, t4 = lane & 3;
    const int h = blockIdx.x;

#pragma unroll
    for (int mi = 0; mi < 4; mi++) {
#pragma unroll
        for (int ni = 0; ni < 8; ni++) {
            int m0 = row0 + warpM * 64 + mi * 16 + g;
            int d  = warpN * 64 + ni * 8 + t4 * 2;
            float v0 = acc[mi][ni][0], v1 = acc[mi][ni][1];
            float v2 = acc[mi][ni][2], v3 = acc[mi][ni][3];
            int b0i = m0 >> 11, s0 = m0 & 2047;
            int b1i = (m0 + 8) >> 11, s1 = (m0 + 8) & 2047;
            if (dorope) {
                int p = d >> 1;
                float c0 = g_cos[s0 * 64 + p], sn0 = g_sin[s0 * 64 + p];
                float c1 = g_cos[s1 * 64 + p], sn1 = g_sin[s1 * 64 + p];
                float r0 = v0 * c0 - v1 * sn0, r1 = v0 * sn0 + v1 * c0;
                float r2 = v2 * c1 - v3 * sn1, r3 = v2 * sn1 + v3 * c1;
                v0 = r0; v1 = r1; v2 = r2; v3 = r3;
            }
            size_t i0 = ((size_t)(b0i * HH + h) * SS + s0) * HD + d;
            size_t i1 = ((size_t)(b1i * HH + h) * SS + s1) * HD + d;
            uint32_t hp, lp;
            split2(v0, v1, hp, lp);
            *(uint32_t*)&Oh[i0] = hp;
            *(uint32_t*)&Ol[i0] = lp;
            split2(v2, v3, hp, lp);
            *(uint32_t*)&Oh[i1] = hp;
            *(uint32_t*)&Ol[i1] = lp;
        }
    }
}

// ---------------- output projection + bias -----------------------------------
__global__ void __launch_bounds__(GEMM_THREADS, 2) gemm_o_kernel(
    const __nv_bfloat16* __restrict__ Ah, const __nv_bfloat16* __restrict__ Al,
    const __nv_bfloat16* __restrict__ Bh, const __nv_bfloat16* __restrict__ Bl,
    const float* __restrict__ bias, float* __restrict__ C)
{
    extern __shared__ uint32_t sm4[];
    uint32_t sb = smem_u32(sm4);
    const int row0 = blockIdx.y * 128;
    const int col0 = blockIdx.x * 128;

    float acc[4][8][4];
    gemm_core(Ah + (size_t)row0 * DD, Al + (size_t)row0 * DD,
              Bh + (size_t)col0 * DD, Bl + (size_t)col0 * DD, sb, acc);

    const int lane = threadIdx.x & 31, wid = threadIdx.x >> 5;
    const int warpM = wid & 1, warpN = wid >> 1;
    const int g = lane >> 2, t4 = lane & 3;

#pragma unroll
    for (int mi = 0; mi < 4; mi++) {
#pragma unroll
        for (int ni = 0; ni < 8; ni++) {
            int m0 = row0 + warpM * 64 + mi * 16 + g;
            int n  = col0 + warpN * 64 + ni * 8 + t4 * 2;
            float b0 = bias[n], b1 = bias[n + 1];
            *(float2*)&C[(size_t)m0 * DD + n] =
                make_float2(acc[mi][ni][0] + b0, acc[mi][ni][1] + b1);
            *(float2*)&C[(size_t)(m0 + 8) * DD + n] =
                make_float2(acc[mi][ni][2] + b0, acc[mi][ni][3] + b1);
        }
    }
}

// ---------------- HMMA flash attention, single-sync pipeline (R12) -----------
#define AT_QH 0
#define AT_QL 9216
#define AT_KV 18432
#define AT_STG 18432
#define ATT_SMEM (55296*4)   // 221184 B

__global__ void __launch_bounds__(256, 1) attn_mma_kernel(
    const __nv_bfloat16* __restrict__ Qh, const __nv_bfloat16* __restrict__ Ql,
    const __nv_bfloat16* __restrict__ Kh, const __nv_bfloat16* __restrict__ Kl,
    const __nv_bfloat16* __restrict__ Vh, const __nv_bfloat16* __restrict__ Vl,
    __nv_bfloat16* __restrict__ CH, __nv_bfloat16* __restrict__ CL)
{
    extern __shared__ uint32_t smw[];
    uint32_t sb = smem_u32(smw);
    const int tid = threadIdx.x, lane = tid & 31, w = tid >> 5;
    const int g = lane >> 2, t4 = lane & 3;
    const int bh = blockIdx.y;
    const int bidx = bh / HH, hidx = bh % HH;
    const int qb = gridDim.x - 1 - blockIdx.x;
    const int q0 = qb * 128;
    const int nkt = qb * 2 + 2;
    const size_t hb = (size_t)bh * SS * HD;

    const int l16 = lane & 15, lh2 = lane >> 4;
    const int bkey = (lane & 7) | ((lane >> 4) << 3);
    const int bch  = (lane >> 3) & 1;
    const int vkey = (lane & 7) | (((lane >> 3) & 1) << 3);
    const int vch  = lane >> 4;

    {
        const __nv_bfloat16* qs0 = Qh + hb + (size_t)q0 * HD;
        const __nv_bfloat16* qs1 = Ql + hb + (size_t)q0 * HD;
#pragma unroll
        for (int i = 0; i < 16; i++) {
            int idx = tid + i * 256;
            int pl = idx >> 11;
            int c = idx & 2047;
            int row = c >> 4;
            int piece = c & 15;
            uint32_t dw = (pl ? AT_QL : AT_QH) + (piece >> 3) * 4608
                        + row * 36 + (piece & 7) * 4;
            cp16(sb + dw * 4, (pl ? qs1 : qs0) + (size_t)row * HD + piece * 8);
        }
    }
    const __nv_bfloat16* kvsrc[4] = {Kh + hb, Kl + hb, Vh + hb, Vl + hb};
    auto load_k = [&](int kt, int buf) {
        int k0 = kt * 64;
#pragma unroll
        for (int i = 0; i < 8; i++) {
            int idx = tid + i * 256;
            int pl = idx >> 10;
            int c = idx & 1023;
            int row = c >> 4;
            int piece = c & 15;
            uint32_t dw = AT_KV + buf * AT_STG + pl * 4608 + (piece >> 3) * 2304
                        + row * 36 + (piece & 7) * 4;
            cp16(sb + dw * 4, kvsrc[pl] + (size_t)(k0 + row) * HD + piece * 8);
        }
    };
    auto load_v = [&](int kt, int buf) {
        int k0 = kt * 64;
#pragma unroll
        for (int i = 0; i < 8; i++) {
            int idx = tid + i * 256;
            int pl = idx >> 10;
            int c = idx & 1023;
            int row = c >> 4;
            int piece = c & 15;
            uint32_t dw = AT_KV + buf * AT_STG + (2 + pl) * 4608 + (piece >> 3) * 2304
                        + row * 36 + (piece & 7) * 4;
            cp16(sb + dw * 4, kvsrc[2 + pl] + (size_t)(k0 + row) * HD + piece * 8);
        }
    };

    float ofr[16][4];
#pragma unroll
    for (int i = 0; i < 16; i++)
#pragma unroll
        for (int j = 0; j < 4; j++) ofr[i][j] = 0.f;
    float m0 = -1e30f, m1 = -1e30f, l0 = 0.f, l1 = 0.f;
    const float scale = 0.08838834764831845f;
    const uint32_t qwoff = (uint32_t)(w * 16 + l16) * 36;
    const int rowg = q0 + w * 16 + g;

    float sf[8][4];

    auto qk_into = [&](int buf) {
        uint32_t stg = AT_KV + (uint32_t)buf * AT_STG;
#pragma unroll
        for (int n = 0; n < 8; n++)
#pragma unroll
            for (int c = 0; c < 4; c++) sf[n][c] = 0.f;
#pragma unroll
        for (int ks = 0; ks < 8; ks++) {
            uint32_t qwo = ((uint32_t)(ks >> 2) * 4608 + qwoff + (ks & 3) * 8 + lh2 * 4) * 4;
            uint32_t qh4[4], ql4[4];
            ldsm_x4(qh4, sb + AT_QH * 4 + qwo);
            ldsm_x4(ql4, sb + AT_QL * 4 + qwo);
            uint32_t khf[8][2], klf[8][2];
#pragma unroll
            for (int j = 0; j < 4; j++) {
                uint32_t kwo = (stg + (uint32_t)(ks >> 2) * 2304
                              + (uint32_t)(j * 16 + bkey) * 36 + (ks & 3) * 8 + bch * 4) * 4;
                uint32_t r[4];
                ldsm_x4(r, sb + kwo);
                khf[2*j][0] = r[0]; khf[2*j][1] = r[1];
                khf[2*j+1][0] = r[2]; khf[2*j+1][1] = r[3];
                ldsm_x4(r, sb + kwo + 4608 * 4);
                klf[2*j][0] = r[0]; klf[2*j][1] = r[1];
                klf[2*j+1][0] = r[2]; klf[2*j+1][1] = r[3];
            }
#pragma unroll
            for (int n = 0; n < 8; n++) {
                mma16816(sf[n], qh4, khf[n]);
                mma16816(sf[n], qh4, klf[n]);
                mma16816(sf[n], ql4, khf[n]);
            }
        }
    };

    load_k(0, 0); load_v(0, 0); CP_COMMIT();
    load_k(1, 1); CP_COMMIT();
    CP_WAIT(0);
    __syncthreads();
    qk_into(0);

    for (int t = 0; t < nkt; t++) {
        const int buf = t & 1;
        CP_WAIT(0);
        __syncthreads();
        if (t + 2 < nkt) load_k(t + 2, buf);
        if (t + 1 < nkt) load_v(t + 1, buf ^ 1);
        CP_COMMIT();

        const bool act = !(t == nkt - 1 && w < 4);
        const bool actnext = (t + 1 < nkt) && !((t + 1) == nkt - 1 && w < 4);

        uint32_t ph[4][4], plo[4][4];
        if (act) {
            int k0 = t * 64;
            bool domask = (t >= nkt - 2);
            float mx0 = -1e30f, mx1 = -1e30f;
#pragma unroll
            for (int n = 0; n < 8; n++) {
#pragma unroll
                for (int c = 0; c < 4; c++) {
                    float v = sf[n][c] * scale;
                    if (domask) {
                        int col = k0 + n * 8 + 2 * t4 + (c & 1);
                        int row = rowg + ((c >> 1) << 3);
                        if (col > row) v = -1e30f;
                    }
                    sf[n][c] = v;
                    if (c < 2) mx0 = fmaxf(mx0, v); else mx1 = fmaxf(mx1, v);
                }
            }
            mx0 = fmaxf(mx0, __shfl_xor_sync(0xffffffffu, mx0, 1));
            mx0 = fmaxf(mx0, __shfl_xor_sync(0xffffffffu, mx0, 2));
            mx1 = fmaxf(mx1, __shfl_xor_sync(0xffffffffu, mx1, 1));
            mx1 = fmaxf(mx1, __shfl_xor_sync(0xffffffffu, mx1, 2));
            float mn0 = fmaxf(m0, mx0), mn1 = fmaxf(m1, mx1);
            float a0 = fexp(m0 - mn0), a1 = fexp(m1 - mn1);
            m0 = mn0; m1 = mn1;
            float s0 = 0.f, s1 = 0.f;
#pragma unroll
            for (int n = 0; n < 8; n++) {
                sf[n][0] = fexp(sf[n][0] - mn0); s0 += sf[n][0];
                sf[n][1] = fexp(sf[n][1] - mn0); s0 += sf[n][1];
                sf[n][2] = fexp(sf[n][2] - mn1); s1 += sf[n][2];
                sf[n][3] = fexp(sf[n][3] - mn1); s1 += sf[n][3];
            }
            s0 += __shfl_xor_sync(0xffffffffu, s0, 1);
            s0 += __shfl_xor_sync(0xffffffffu, s0, 2);
            s1 += __shfl_xor_sync(0xffffffffu, s1, 1);
            s1 += __shfl_xor_sync(0xffffffffu, s1, 2);
            l0 = l0 * a0 + s0;
            l1 = l1 * a1 + s1;
#pragma unroll
            for (int nc = 0; nc < 16; nc++) {
                ofr[nc][0] *= a0; ofr[nc][1] *= a0;
                ofr[nc][2] *= a1; ofr[nc][3] *= a1;
            }
#pragma unroll
            for (int kb = 0; kb < 4; kb++) {
                split2(sf[2*kb][0],   sf[2*kb][1],   ph[kb][0], plo[kb][0]);
                split2(sf[2*kb][2],   sf[2*kb][3],   ph[kb][1], plo[kb][1]);
                split2(sf[2*kb+1][0], sf[2*kb+1][1], ph[kb][2], plo[kb][2]);
                split2(sf[2*kb+1][2], sf[2*kb+1][3], ph[kb][3], plo[kb][3]);
            }
        }

        if (actnext) qk_into(buf ^ 1);

        if (act) {
            uint32_t stg = AT_KV + (uint32_t)buf * AT_STG;
#pragma unroll
            for (int kb = 0; kb < 4; kb++) {
                uint32_t krow = (uint32_t)(kb * 16 + vkey) * 36;
#pragma unroll
                for (int jj = 0; jj < 8; jj++) {
                    int cj = jj * 2 + vch;
                    uint32_t vwo = (stg + 9216u + (uint32_t)(cj >> 3) * 2304
                                  + krow + (uint32_t)(cj & 7) * 4) * 4;
                    uint32_t rv[4], rl[4];
                    ldsm_x4_t(rv, sb + vwo);
                    ldsm_x4_t(rl, sb + vwo + 4608 * 4);
                    mma2(ofr[2*jj],   ph[kb], rv[0], rv[1]);
                    mma2(ofr[2*jj],   ph[kb], rl[0], rl[1]);
                    mma2(ofr[2*jj],   plo[kb], rv[0], rv[1]);
                    mma2(ofr[2*jj+1], ph[kb], rv[2], rv[3]);
                    mma2(ofr[2*jj+1], ph[kb], rl[2], rl[3]);
                    mma2(ofr[2*jj+1], plo[kb], rv[2], rv[3]);
                }
            }
        }
    }

    float i0 = 1.f / l0, i1 = 1.f / l1;
    int r0 = q0 + w * 16 + g, r1 = r0 + 8;
    size_t base0 = ((size_t)(bidx * SS + r0)) * DD + hidx * HD;
    size_t base1 = ((size_t)(bidx * SS + r1)) * DD + hidx * HD;
#pragma unroll
    for (int nc = 0; nc < 16; nc++) {
        int d = nc * 8 + 2 * t4;
        uint32_t hp, lp;
        split2(ofr[nc][0] * i0, ofr[nc][1] * i0, hp, lp);
        *(uint32_t*)&CH[base0 + d] = hp;
        *(uint32_t*)&CL[base0 + d] = lp;
        split2(ofr[nc][2] * i1, ofr[nc][3] * i1, hp, lp);
        *(uint32_t*)&CH[base1 + d] = hp;
        *(uint32_t*)&CL[base1 + d] = lp;
    }
}

// ---------------------------------------------------------------------------
extern "C" void kernel_launch(void* const* d_in, const int* in_sizes, int n_in,
                              void* d_out, int out_size)
{
    const float* x  = (const float*)d_in[0];
    const float* wq = (const float*)d_in[1];
    const float* wk = (const float*)d_in[2];
    const float* wv = (const float*)d_in[3];
    const float* wo = (const float*)d_in[4];
    const float* bo = (const float*)d_in[5];
    float* out = (float*)d_out;

    __nv_bfloat16 *qh, *ql, *kh, *kl, *vh, *vl, *xh, *xl, *wh, *wl, *ch, *cl;
    cudaGetSymbolAddress((void**)&qh, g_qh);
    cudaGetSymbolAddress((void**)&ql, g_ql);
    cudaGetSymbolAddress((void**)&kh, g_kh);
    cudaGetSymbolAddress((void**)&kl, g_kl);
    cudaGetSymbolAddress((void**)&vh, g_vh);
    cudaGetSymbolAddress((void**)&vl, g_vl);
    cudaGetSymbolAddress((void**)&xh, g_xh);
    cudaGetSymbolAddress((void**)&xl, g_xl);
    cudaGetSymbolAddress((void**)&wh, g_wh);
    cudaGetSymbolAddress((void**)&wl, g_wl);
    cudaGetSymbolAddress((void**)&ch, g_ch);
    cudaGetSymbolAddress((void**)&cl, g_cl);

    cudaFuncSetAttribute(gemm_qkv_kernel, cudaFuncAttributeMaxDynamicSharedMemorySize, GEMM_SMEM);
    cudaFuncSetAttribute(gemm_o_kernel,   cudaFuncAttributeMaxDynamicSharedMemorySize, GEMM_SMEM);
    cudaFuncSetAttribute(attn_mma_kernel, cudaFuncAttributeMaxDynamicSharedMemorySize, ATT_SMEM);

    // launch order: gemm_o is the 4th launch -> lands in the ncu capture slot
    cvt_all_kernel<<<(CVT_TOTAL + 255) / 256, 256>>>(                         // 1
        x, wq, wk, wv, wo, xh, xl, wh, wl);

    gemm_qkv_kernel<<<dim3(DD / 128, MM / 128, 3), GEMM_THREADS, GEMM_SMEM>>>(// 2
        xh, xl, wh, wl, qh, ql, kh, kl, vh, vl);

    attn_mma_kernel<<<dim3(SS / 128, BB * HH), 256, ATT_SMEM>>>(              // 3
        qh, ql, kh, kl, vh, vl, ch, cl);

    gemm_o_kernel<<<dim3(DD / 128, MM / 128), GEMM_THREADS, GEMM_SMEM>>>(     // 4
        ch, cl, wh + (size_t)3 * DD * DD, wl + (size_t)3 * DD * DD, bo, out);
}

// round 17
// speedup vs baseline: 1.0094x; 1.0090x over previous
#include <cuda_runtime.h>
#include <cuda_bf16.h>
#include <math.h>
#include <stdint.h>

#define BB 4
#define SS 2048
#define DD 2048
#define HH 16
#define HD 128
#define MM (BB*SS)   // 8192

// ---------------- scratch (device globals: allocation-free rule) -----------
__device__ __nv_bfloat16 g_qh[(size_t)BB*HH*SS*HD];
__device__ __nv_bfloat16 g_ql[(size_t)BB*HH*SS*HD];
__device__ __nv_bfloat16 g_kh[(size_t)BB*HH*SS*HD];
__device__ __nv_bfloat16 g_kl[(size_t)BB*HH*SS*HD];
__device__ __nv_bfloat16 g_vh[(size_t)BB*HH*SS*HD];
__device__ __nv_bfloat16 g_vl[(size_t)BB*HH*SS*HD];
__device__ __nv_bfloat16 g_xh[(size_t)MM*DD];
__device__ __nv_bfloat16 g_xl[(size_t)MM*DD];
__device__ __nv_bfloat16 g_wh[(size_t)4*DD*DD];
__device__ __nv_bfloat16 g_wl[(size_t)4*DD*DD];
__device__ __nv_bfloat16 g_ch[(size_t)MM*DD];
__device__ __nv_bfloat16 g_cl[(size_t)MM*DD];
__device__ float g_cos[SS*64];
__device__ float g_sin[SS*64];

// ---------------- helpers ----------------------------------------------------
__device__ __forceinline__ uint32_t smem_u32(const void* p) {
    uint32_t a;
    asm("{ .reg .u64 t; cvta.to.shared.u64 t, %1; cvt.u32.u64 %0, t; }"
        : "=r"(a) : "l"(p));
    return a;
}
__device__ __forceinline__ void cp16(uint32_t dst, const void* src) {
    asm volatile("cp.async.cg.shared.global [%0], [%1], 16;" :: "r"(dst), "l"(src));
}
#define CP_COMMIT() asm volatile("cp.async.commit_group;" ::: "memory")
#define CP_WAIT(n)  asm volatile("cp.async.wait_group %0;" :: "n"(n) : "memory")

__device__ __forceinline__ void mma16816(float* c, const uint32_t* a, const uint32_t* b) {
    asm volatile(
        "mma.sync.aligned.m16n8k16.row.col.f32.bf16.bf16.f32 "
        "{%0,%1,%2,%3}, {%4,%5,%6,%7}, {%8,%9}, {%0,%1,%2,%3};"
        : "+f"(c[0]), "+f"(c[1]), "+f"(c[2]), "+f"(c[3])
        : "r"(a[0]), "r"(a[1]), "r"(a[2]), "r"(a[3]), "r"(b[0]), "r"(b[1]));
}
__device__ __forceinline__ void mma2(float* c, const uint32_t* a, uint32_t b0, uint32_t b1) {
    asm volatile(
        "mma.sync.aligned.m16n8k16.row.col.f32.bf16.bf16.f32 "
        "{%0,%1,%2,%3}, {%4,%5,%6,%7}, {%8,%9}, {%0,%1,%2,%3};"
        : "+f"(c[0]), "+f"(c[1]), "+f"(c[2]), "+f"(c[3])
        : "r"(a[0]), "r"(a[1]), "r"(a[2]), "r"(a[3]), "r"(b0), "r"(b1));
}
__device__ __forceinline__ void ldsm_x4(uint32_t* r, uint32_t addr) {
    asm volatile("ldmatrix.sync.aligned.m8n8.x4.shared.b16 {%0,%1,%2,%3}, [%4];"
        : "=r"(r[0]), "=r"(r[1]), "=r"(r[2]), "=r"(r[3]) : "r"(addr));
}
__device__ __forceinline__ void ldsm_x4_t(uint32_t* r, uint32_t addr) {
    asm volatile("ldmatrix.sync.aligned.m8n8.x4.trans.shared.b16 {%0,%1,%2,%3}, [%4];"
        : "=r"(r[0]), "=r"(r[1]), "=r"(r[2]), "=r"(r[3]) : "r"(addr));
}
__device__ __forceinline__ uint32_t packbf(float lo, float hi) {
    uint32_t r;
    asm("cvt.rn.bf16x2.f32 %0, %1, %2;" : "=r"(r) : "f"(hi), "f"(lo));
    return r;
}
__device__ __forceinline__ void split2(float x, float y, uint32_t& hp, uint32_t& lp) {
    hp = packbf(x, y);
    float hx = __int_as_float(hp << 16);
    float hy = __int_as_float(hp & 0xFFFF0000u);
    lp = packbf(x - hx, y - hy);
}
// fast exp on FMA/ALU pipes (x <= ~0), rel err ~2e-6
__device__ __forceinline__ float fexp(float x) {
    float y = fmaxf(x * 1.4426950408889634f, -120.f);
    float t = y + 12582912.f;
    int n = __float_as_int(t) - 0x4B400000;
    float f = y - (t - 12582912.f);
    float p = 1.3333558146e-3f;
    p = fmaf(p, f, 9.6181291076e-3f);
    p = fmaf(p, f, 5.5504108665e-2f);
    p = fmaf(p, f, 2.4022650696e-1f);
    p = fmaf(p, f, 6.9314718056e-1f);
    p = fmaf(p, f, 1.0f);
    return p * __int_as_float((127 + n) << 23);
}

// ---------------- unified conversion kernel (x, 4 weights, rope) -------------
__device__ __forceinline__ void split8(const float* in, __nv_bfloat16* hi,
                                       __nv_bfloat16* lo, int i) {
    float4 v0 = ((const float4*)in)[2 * i];
    float4 v1 = ((const float4*)in)[2 * i + 1];
    float a[8] = {v0.x, v0.y, v0.z, v0.w, v1.x, v1.y, v1.z, v1.w};
    __align__(16) __nv_bfloat16 h[8], l[8];
#pragma unroll
    for (int j = 0; j < 8; j++) {
        h[j] = __float2bfloat16(a[j]);
        l[j] = __float2bfloat16(a[j] - __bfloat162float(h[j]));
    }
    *(uint4*)&hi[(size_t)i * 8] = *(uint4*)h;
    *(uint4*)&lo[(size_t)i * 8] = *(uint4*)l;
}

#define XN8 (MM*DD/8)     // 2097152
#define WN8 (DD*DD/8)     // 524288 = 2^19
#define CVT_TOTAL (XN8 + 4*WN8 + SS*64)

__global__ void cvt_all_kernel(const float* __restrict__ x,
                               const float* __restrict__ wq, const float* __restrict__ wk,
                               const float* __restrict__ wv, const float* __restrict__ wo,
                               __nv_bfloat16* __restrict__ xh, __nv_bfloat16* __restrict__ xl,
                               __nv_bfloat16* __restrict__ wh, __nv_bfloat16* __restrict__ wl)
{
    int i = blockIdx.x * blockDim.x + threadIdx.x;
    if (i < XN8) { split8(x, xh, xl, i); return; }
    i -= XN8;
    if (i < 4 * WN8) {
        int wsel = i >> 19;
        int j = i & (WN8 - 1);
        const float* w = (wsel == 0) ? wq : (wsel == 1) ? wk : (wsel == 2) ? wv : wo;
        split8(w, wh + (size_t)wsel * DD * DD, wl + (size_t)wsel * DD * DD, j);
        return;
    }
    i -= 4 * WN8;
    if (i < SS * 64) {
        int s = i >> 6, p = i & 63;
        double invf = exp(-(double)p * (log(10000.0) / 64.0));
        float ang = (float)s * (float)invf;
        float sv, cv;
        sincosf(ang, &sv, &cv);
        g_cos[i] = cv;
        g_sin[i] = sv;
    }
}

// ---------------- shared GEMM mainloop (64x64 warp tile, pass-reordered) ------
#define KSTG    32
#define TWORDS  2048                 // 128 rows * 16 words
#define SWORDS  (4*TWORDS)           // 8192 words = 32 KB per stage
#define GEMM_SMEM (3*SWORDS*4)       // 98304 bytes -> 2 CTAs/SM
#define NSTG    (DD/KSTG)            // 64
#define GEMM_THREADS 128

__device__ __forceinline__ void gemm_core(
    const __nv_bfloat16* __restrict__ src0, const __nv_bfloat16* __restrict__ src1,
    const __nv_bfloat16* __restrict__ src2, const __nv_bfloat16* __restrict__ src3,
    uint32_t sb, float (&acc)[4][8][4])
{
    const int tid  = threadIdx.x;
    const int lane = tid & 31;
    const int wid  = tid >> 5;           // 0..3
    const int warpM = wid & 1;
    const int warpN = wid >> 1;          // 0..1
    const int l16 = lane & 15, lh2 = lane >> 4;
    const int bkey = (lane & 7) | ((lane >> 4) << 3);
    const int bch  = (lane >> 3) & 1;

    const __nv_bfloat16* srcs[4] = {src0, src1, src2, src3};

#pragma unroll
    for (int mi = 0; mi < 4; mi++)
#pragma unroll
        for (int ni = 0; ni < 8; ni++)
#pragma unroll
            for (int j = 0; j < 4; j++) acc[mi][ni][j] = 0.f;

    auto load_stage = [&](int kt, int slot) {
        const int k0 = kt * KSTG;
        uint32_t base = sb + (uint32_t)slot * SWORDS * 4;
#pragma unroll
        for (int t = 0; t < 4; t++) {
            const __nv_bfloat16* src = srcs[t] + k0;
            uint32_t db = base + (uint32_t)t * TWORDS * 4;
#pragma unroll
            for (int q = 0; q < 4; q++) {
                int idx = tid + q * GEMM_THREADS;   // 0..511
                int r = idx >> 2;                    // row 0..127
                int c = idx & 3;                     // 16B chunk 0..3
                int pos = (c ^ ((r >> 1) & 3)) & 3;
                cp16(db + (uint32_t)(r * 16 + pos * 4) * 4,
                     src + (size_t)r * DD + c * 8);
            }
        }
    };

    load_stage(0, 0); CP_COMMIT();
    load_stage(1, 1); CP_COMMIT();

    int aR[4], aS[4];
#pragma unroll
    for (int mi = 0; mi < 4; mi++) {
        aR[mi] = warpM * 64 + mi * 16 + l16;
        aS[mi] = (aR[mi] >> 1) & 3;
    }
    int bR[4], bS[4];
#pragma unroll
    for (int jj = 0; jj < 4; jj++) {
        bR[jj] = warpN * 64 + jj * 16 + bkey;
        bS[jj] = (bR[jj] >> 1) & 3;
    }

    int slot = 0;
    for (int kt = 0; kt < NSTG; kt++) {
        CP_WAIT(1);          // load(kt) landed
        __syncthreads();     // ring slot reuse safe
        if (kt + 2 < NSTG) {
            int s2 = slot - 1; if (s2 < 0) s2 = 2;   // (kt+2) % 3
            load_stage(kt + 2, s2);
        }
        CP_COMMIT();         // one group per stage keeps wait algebra fixed

        uint32_t tb = sb + (uint32_t)slot * SWORDS * 4;
        uint32_t pAh = tb;
        uint32_t pAl = tb + TWORDS * 4;
        uint32_t pBh = tb + 2 * TWORDS * 4;
        uint32_t pBl = tb + 3 * TWORDS * 4;

#pragma unroll
        for (int ks = 0; ks < 2; ks++) {
            uint32_t ah[4][4], al[4][4], bf[8][2];
            int ja = ks * 2 + lh2;
#pragma unroll
            for (int mi = 0; mi < 4; mi++) {
                uint32_t wo = (uint32_t)(aR[mi] * 16 + ((ja ^ aS[mi]) & 3) * 4) * 4;
                ldsm_x4(ah[mi], pAh + wo);
                ldsm_x4(al[mi], pAl + wo);
            }
            int jb = ks * 2 + bch;
            // B-hi plane
#pragma unroll
            for (int jj = 0; jj < 4; jj++) {
                uint32_t wo = (uint32_t)(bR[jj] * 16 + ((jb ^ bS[jj]) & 3) * 4) * 4;
                uint32_t r[4];
                ldsm_x4(r, pBh + wo);
                bf[2*jj][0] = r[0]; bf[2*jj][1] = r[1];
                bf[2*jj+1][0] = r[2]; bf[2*jj+1][1] = r[3];
            }
            // pass 1: ah*bh over all 32 accumulators (same-acc distance = 32)
#pragma unroll
            for (int mi = 0; mi < 4; mi++)
#pragma unroll
                for (int ni = 0; ni < 8; ni++)
                    mma16816(acc[mi][ni], ah[mi], bf[ni]);
            // pass 2: al*bh
#pragma unroll
            for (int mi = 0; mi < 4; mi++)
#pragma unroll
                for (int ni = 0; ni < 8; ni++)
                    mma16816(acc[mi][ni], al[mi], bf[ni]);
            // B-lo plane
#pragma unroll
            for (int jj = 0; jj < 4; jj++) {
                uint32_t wo = (uint32_t)(bR[jj] * 16 + ((jb ^ bS[jj]) & 3) * 4) * 4;
                uint32_t r[4];
                ldsm_x4(r, pBl + wo);
                bf[2*jj][0] = r[0]; bf[2*jj][1] = r[1];
                bf[2*jj+1][0] = r[2]; bf[2*jj+1][1] = r[3];
            }
            // pass 3: ah*bl
#pragma unroll
            for (int mi = 0; mi < 4; mi++)
#pragma unroll
                for (int ni = 0; ni < 8; ni++)
                    mma16816(acc[mi][ni], ah[mi], bf[ni]);
        }
        slot = (slot == 2) ? 0 : slot + 1;
    }
}

// ---------------- fused QKV projection (z = 0:Q, 1:K, 2:V) -------------------
__global__ void __launch_bounds__(GEMM_THREADS, 2) gemm_qkv_kernel(
    const __nv_bfloat16* __restrict__ Xh, const __nv_bfloat16* __restrict__ Xl,
    const __nv_bfloat16* __restrict__ Wh, const __nv_bfloat16* __restrict__ Wl,
    __nv_bfloat16* __restrict__ Qh, __nv_bfloat16* __restrict__ Ql,
    __nv_bfloat16* __restrict__ Kh, __nv_bfloat16* __restrict__ Kl,
    __nv_bfloat16* __restrict__ Vh, __nv_bfloat16* __restrict__ Vl)
{
    extern __shared__ uint32_t sm4[];
    uint32_t sb = smem_u32(sm4);
    const int z = blockIdx.z;
    const int row0 = blockIdx.y * 128;
    const int col0 = blockIdx.x * 128;
    const __nv_bfloat16* Bh = Wh + (size_t)z * DD * DD + (size_t)col0 * DD;
    const __nv_bfloat16* Bl = Wl + (size_t)z * DD * DD + (size_t)col0 * DD;

    float acc[4][8][4];
    gemm_core(Xh + (size_t)row0 * DD, Xl + (size_t)row0 * DD, Bh, Bl, sb, acc);

    __nv_bfloat16* Oh = (z == 0) ? Qh : (z == 1) ? Kh : Vh;
    __nv_bfloat16* Ol = (z == 0) ? Ql : (z == 1) ? Kl : Vl;
    const bool dorope = (z < 2);

    const int lane = threadIdx.x & 31, wid = threadIdx.x >> 5;
    const int warpM = wid & 1, warpN = wid >> 1;
    const int g = lane >> 2, t4 = lane & 3;
    const int h = blockIdx.x;

#pragma unroll
    for (int mi = 0; mi < 4; mi++) {
#pragma unroll
        for (int ni = 0; ni < 8; ni++) {
            int m0 = row0 + warpM * 64 + mi * 16 + g;
            int d  = warpN * 64 + ni * 8 + t4 * 2;
            float v0 = acc[mi][ni][0], v1 = acc[mi][ni][1];
            float v2 = acc[mi][ni][2], v3 = acc[mi][ni][3];
            int b0i = m0 >> 11, s0 = m0 & 2047;
            int b1i = (m0 + 8) >> 11, s1 = (m0 + 8) & 2047;
            if (dorope) {
                int p = d >> 1;
                float c0 = g_cos[s0 * 64 + p], sn0 = g_sin[s0 * 64 + p];
                float c1 = g_cos[s1 * 64 + p], sn1 = g_sin[s1 * 64 + p];
                float r0 = v0 * c0 - v1 * sn0, r1 = v0 * sn0 + v1 * c0;
                float r2 = v2 * c1 - v3 * sn1, r3 = v2 * sn1 + v3 * c1;
                v0 = r0; v1 = r1; v2 = r2; v3 = r3;
            }
            size_t i0 = ((size_t)(b0i * HH + h) * SS + s0) * HD + d;
            size_t i1 = ((size_t)(b1i * HH + h) * SS + s1) * HD + d;
            uint32_t hp, lp;
            split2(v0, v1, hp, lp);
            *(uint32_t*)&Oh[i0] = hp;
            *(uint32_t*)&Ol[i0] = lp;
            split2(v2, v3, hp, lp);
            *(uint32_t*)&Oh[i1] = hp;
            *(uint32_t*)&Ol[i1] = lp;
        }
    }
}

// ---------------- output projection + bias -----------------------------------
__global__ void __launch_bounds__(GEMM_THREADS, 2) gemm_o_kernel(
    const __nv_bfloat16* __restrict__ Ah, const __nv_bfloat16* __restrict__ Al,
    const __nv_bfloat16* __restrict__ Bh, const __nv_bfloat16* __restrict__ Bl,
    const float* __restrict__ bias, float* __restrict__ C)
{
    extern __shared__ uint32_t sm4[];
    uint32_t sb = smem_u32(sm4);
    const int row0 = blockIdx.y * 128;
    const int col0 = blockIdx.x * 128;

    float acc[4][8][4];
    gemm_core(Ah + (size_t)row0 * DD, Al + (size_t)row0 * DD,
              Bh + (size_t)col0 * DD, Bl + (size_t)col0 * DD, sb, acc);

    const int lane = threadIdx.x & 31, wid = threadIdx.x >> 5;
    const int warpM = wid & 1, warpN = wid >> 1;
    const int g = lane >> 2, t4 = lane & 3;

#pragma unroll
    for (int mi = 0; mi < 4; mi++) {
#pragma unroll
        for (int ni = 0; ni < 8; ni++) {
            int m0 = row0 + warpM * 64 + mi * 16 + g;
            int n  = col0 + warpN * 64 + ni * 8 + t4 * 2;
            float b0 = bias[n], b1 = bias[n + 1];
            *(float2*)&C[(size_t)m0 * DD + n] =
                make_float2(acc[mi][ni][0] + b0, acc[mi][ni][1] + b1);
            *(float2*)&C[(size_t)(m0 + 8) * DD + n] =
                make_float2(acc[mi][ni][2] + b0, acc[mi][ni][3] + b1);
        }
    }
}

// ---------------- HMMA flash attention, single-sync, pass-reordered ----------
#define AT_QH 0
#define AT_QL 9216
#define AT_KV 18432
#define AT_STG 18432
#define ATT_SMEM (55296*4)   // 221184 B

__global__ void __launch_bounds__(256, 1) attn_mma_kernel(
    const __nv_bfloat16* __restrict__ Qh, const __nv_bfloat16* __restrict__ Ql,
    const __nv_bfloat16* __restrict__ Kh, const __nv_bfloat16* __restrict__ Kl,
    const __nv_bfloat16* __restrict__ Vh, const __nv_bfloat16* __restrict__ Vl,
    __nv_bfloat16* __restrict__ CH, __nv_bfloat16* __restrict__ CL)
{
    extern __shared__ uint32_t smw[];
    uint32_t sb = smem_u32(smw);
    const int tid = threadIdx.x, lane = tid & 31, w = tid >> 5;
    const int g = lane >> 2, t4 = lane & 3;
    const int bh = blockIdx.y;
    const int bidx = bh / HH, hidx = bh % HH;
    const int qb = gridDim.x - 1 - blockIdx.x;
    const int q0 = qb * 128;
    const int nkt = qb * 2 + 2;
    const size_t hb = (size_t)bh * SS * HD;

    const int l16 = lane & 15, lh2 = lane >> 4;
    const int bkey = (lane & 7) | ((lane >> 4) << 3);
    const int bch  = (lane >> 3) & 1;
    const int vkey = (lane & 7) | (((lane >> 3) & 1) << 3);
    const int vch  = lane >> 4;

    {
        const __nv_bfloat16* qs0 = Qh + hb + (size_t)q0 * HD;
        const __nv_bfloat16* qs1 = Ql + hb + (size_t)q0 * HD;
#pragma unroll
        for (int i = 0; i < 16; i++) {
            int idx = tid + i * 256;
            int pl = idx >> 11;
            int c = idx & 2047;
            int row = c >> 4;
            int piece = c & 15;
            uint32_t dw = (pl ? AT_QL : AT_QH) + (piece >> 3) * 4608
                        + row * 36 + (piece & 7) * 4;
            cp16(sb + dw * 4, (pl ? qs1 : qs0) + (size_t)row * HD + piece * 8);
        }
    }
    const __nv_bfloat16* kvsrc[4] = {Kh + hb, Kl + hb, Vh + hb, Vl + hb};
    auto load_k = [&](int kt, int buf) {
        int k0 = kt * 64;
#pragma unroll
        for (int i = 0; i < 8; i++) {
            int idx = tid + i * 256;
            int pl = idx >> 10;
            int c = idx & 1023;
            int row = c >> 4;
            int piece = c & 15;
            uint32_t dw = AT_KV + buf * AT_STG + pl * 4608 + (piece >> 3) * 2304
                        + row * 36 + (piece & 7) * 4;
            cp16(sb + dw * 4, kvsrc[pl] + (size_t)(k0 + row) * HD + piece * 8);
        }
    };
    auto load_v = [&](int kt, int buf) {
        int k0 = kt * 64;
#pragma unroll
        for (int i = 0; i < 8; i++) {
            int idx = tid + i * 256;
            int pl = idx >> 10;
            int c = idx & 1023;
            int row = c >> 4;
            int piece = c & 15;
            uint32_t dw = AT_KV + buf * AT_STG + (2 + pl) * 4608 + (piece >> 3) * 2304
                        + row * 36 + (piece & 7) * 4;
            cp16(sb + dw * 4, kvsrc[2 + pl] + (size_t)(k0 + row) * HD + piece * 8);
        }
    };

    float ofr[16][4];
#pragma unroll
    for (int i = 0; i < 16; i++)
#pragma unroll
        for (int j = 0; j < 4; j++) ofr[i][j] = 0.f;
    float m0 = -1e30f, m1 = -1e30f, l0 = 0.f, l1 = 0.f;
    const float scale = 0.08838834764831845f;
    const uint32_t qwoff = (uint32_t)(w * 16 + l16) * 36;
    const int rowg = q0 + w * 16 + g;

    float sf[8][4];

    auto qk_into = [&](int buf) {
        uint32_t stg = AT_KV + (uint32_t)buf * AT_STG;
#pragma unroll
        for (int n = 0; n < 8; n++)
#pragma unroll
            for (int c = 0; c < 4; c++) sf[n][c] = 0.f;
#pragma unroll
        for (int ks = 0; ks < 8; ks++) {
            uint32_t qwo = ((uint32_t)(ks >> 2) * 4608 + qwoff + (ks & 3) * 8 + lh2 * 4) * 4;
            uint32_t qh4[4], ql4[4];
            ldsm_x4(qh4, sb + AT_QH * 4 + qwo);
            ldsm_x4(ql4, sb + AT_QL * 4 + qwo);
            uint32_t khf[8][2], klf[8][2];
#pragma unroll
            for (int j = 0; j < 4; j++) {
                uint32_t kwo = (stg + (uint32_t)(ks >> 2) * 2304
                              + (uint32_t)(j * 16 + bkey) * 36 + (ks & 3) * 8 + bch * 4) * 4;
                uint32_t r[4];
                ldsm_x4(r, sb + kwo);
                khf[2*j][0] = r[0]; khf[2*j][1] = r[1];
                khf[2*j+1][0] = r[2]; khf[2*j+1][1] = r[3];
                ldsm_x4(r, sb + kwo + 4608 * 4);
                klf[2*j][0] = r[0]; klf[2*j][1] = r[1];
                klf[2*j+1][0] = r[2]; klf[2*j+1][1] = r[3];
            }
            // pass-reordered: same-acc distance 8 instead of 1
#pragma unroll
            for (int n = 0; n < 8; n++) mma16816(sf[n], qh4, khf[n]);
#pragma unroll
            for (int n = 0; n < 8; n++) mma16816(sf[n], qh4, klf[n]);
#pragma unroll
            for (int n = 0; n < 8; n++) mma16816(sf[n], ql4, khf[n]);
        }
    };

    load_k(0, 0); load_v(0, 0); CP_COMMIT();
    load_k(1, 1); CP_COMMIT();
    CP_WAIT(0);
    __syncthreads();
    qk_into(0);

    for (int t = 0; t < nkt; t++) {
        const int buf = t & 1;
        CP_WAIT(0);
        __syncthreads();
        if (t + 2 < nkt) load_k(t + 2, buf);
        if (t + 1 < nkt) load_v(t + 1, buf ^ 1);
        CP_COMMIT();

        const bool act = !(t == nkt - 1 && w < 4);
        const bool actnext = (t + 1 < nkt) && !((t + 1) == nkt - 1 && w < 4);

        uint32_t ph[4][4], plo[4][4];
        if (act) {
            int k0 = t * 64;
            bool domask = (t >= nkt - 2);
            float mx0 = -1e30f, mx1 = -1e30f;
#pragma unroll
            for (int n = 0; n < 8; n++) {
#pragma unroll
                for (int c = 0; c < 4; c++) {
                    float v = sf[n][c] * scale;
                    if (domask) {
                        int col = k0 + n * 8 + 2 * t4 + (c & 1);
                        int row = rowg + ((c >> 1) << 3);
                        if (col > row) v = -1e30f;
                    }
                    sf[n][c] = v;
                    if (c < 2) mx0 = fmaxf(mx0, v); else mx1 = fmaxf(mx1, v);
                }
            }
            mx0 = fmaxf(mx0, __shfl_xor_sync(0xffffffffu, mx0, 1));
            mx0 = fmaxf(mx0, __shfl_xor_sync(0xffffffffu, mx0, 2));
            mx1 = fmaxf(mx1, __shfl_xor_sync(0xffffffffu, mx1, 1));
            mx1 = fmaxf(mx1, __shfl_xor_sync(0xffffffffu, mx1, 2));
            float mn0 = fmaxf(m0, mx0), mn1 = fmaxf(m1, mx1);
            float a0 = fexp(m0 - mn0), a1 = fexp(m1 - mn1);
            m0 = mn0; m1 = mn1;
            float s0 = 0.f, s1 = 0.f;
#pragma unroll
            for (int n = 0; n < 8; n++) {
                sf[n][0] = fexp(sf[n][0] - mn0); s0 += sf[n][0];
                sf[n][1] = fexp(sf[n][1] - mn0); s0 += sf[n][1];
                sf[n][2] = fexp(sf[n][2] - mn1); s1 += sf[n][2];
                sf[n][3] = fexp(sf[n][3] - mn1); s1 += sf[n][3];
            }
            s0 += __shfl_xor_sync(0xffffffffu, s0, 1);
            s0 += __shfl_xor_sync(0xffffffffu, s0, 2);
            s1 += __shfl_xor_sync(0xffffffffu, s1, 1);
            s1 += __shfl_xor_sync(0xffffffffu, s1, 2);
            l0 = l0 * a0 + s0;
            l1 = l1 * a1 + s1;
#pragma unroll
            for (int nc = 0; nc < 16; nc++) {
                ofr[nc][0] *= a0; ofr[nc][1] *= a0;
                ofr[nc][2] *= a1; ofr[nc][3] *= a1;
            }
#pragma unroll
            for (int kb = 0; kb < 4; kb++) {
                split2(sf[2*kb][0],   sf[2*kb][1],   ph[kb][0], plo[kb][0]);
                split2(sf[2*kb][2],   sf[2*kb][3],   ph[kb][1], plo[kb][1]);
                split2(sf[2*kb+1][0], sf[2*kb+1][1], ph[kb][2], plo[kb][2]);
                split2(sf[2*kb+1][2], sf[2*kb+1][3], ph[kb][3], plo[kb][3]);
            }
        }

        if (actnext) qk_into(buf ^ 1);

        if (act) {
            uint32_t stg = AT_KV + (uint32_t)buf * AT_STG;
#pragma unroll
            for (int kb = 0; kb < 4; kb++) {
                uint32_t krow = (uint32_t)(kb * 16 + vkey) * 36;
#pragma unroll
                for (int jj = 0; jj < 8; jj++) {
                    int cj = jj * 2 + vch;
                    uint32_t vwo = (stg + 9216u + (uint32_t)(cj >> 3) * 2304
                                  + krow + (uint32_t)(cj & 7) * 4) * 4;
                    uint32_t rv[4], rl[4];
                    ldsm_x4_t(rv, sb + vwo);
                    ldsm_x4_t(rl, sb + vwo + 4608 * 4);
                    // alternate accumulators: same-acc distance 2 instead of 1,
                    // per-accumulator addition order unchanged
                    mma2(ofr[2*jj],   ph[kb], rv[0], rv[1]);
                    mma2(ofr[2*jj+1], ph[kb], rv[2], rv[3]);
                    mma2(ofr[2*jj],   ph[kb], rl[0], rl[1]);
                    mma2(ofr[2*jj+1], ph[kb], rl[2], rl[3]);
                    mma2(ofr[2*jj],   plo[kb], rv[0], rv[1]);
                    mma2(ofr[2*jj+1], plo[kb], rv[2], rv[3]);
                }
            }
        }
    }

    float i0 = 1.f / l0, i1 = 1.f / l1;
    int r0 = q0 + w * 16 + g, r1 = r0 + 8;
    size_t base0 = ((size_t)(bidx * SS + r0)) * DD + hidx * HD;
    size_t base1 = ((size_t)(bidx * SS + r1)) * DD + hidx * HD;
#pragma unroll
    for (int nc = 0; nc < 16; nc++) {
        int d = nc * 8 + 2 * t4;
        uint32_t hp, lp;
        split2(ofr[nc][0] * i0, ofr[nc][1] * i0, hp, lp);
        *(uint32_t*)&CH[base0 + d] = hp;
        *(uint32_t*)&CL[base0 + d] = lp;
        split2(ofr[nc][2] * i1, ofr[nc][3] * i1, hp, lp);
        *(uint32_t*)&CH[base1 + d] = hp;
        *(uint32_t*)&CL[base1 + d] = lp;
    }
}

// ---------------------------------------------------------------------------
extern "C" void kernel_launch(void* const* d_in, const int* in_sizes, int n_in,
                              void* d_out, int out_size)
{
    const float* x  = (const float*)d_in[0];
    const float* wq = (const float*)d_in[1];
    const float* wk = (const float*)d_in[2];
    const float* wv = (const float*)d_in[3];
    const float* wo = (const float*)d_in[4];
    const float* bo = (const float*)d_in[5];
    float* out = (float*)d_out;

    __nv_bfloat16 *qh, *ql, *kh, *kl, *vh, *vl, *xh, *xl, *wh, *wl, *ch, *cl;
    cudaGetSymbolAddress((void**)&qh, g_qh);
    cudaGetSymbolAddress((void**)&ql, g_ql);
    cudaGetSymbolAddress((void**)&kh, g_kh);
    cudaGetSymbolAddress((void**)&kl, g_kl);
    cudaGetSymbolAddress((void**)&vh, g_vh);
    cudaGetSymbolAddress((void**)&vl, g_vl);
    cudaGetSymbolAddress((void**)&xh, g_xh);
    cudaGetSymbolAddress((void**)&xl, g_xl);
    cudaGetSymbolAddress((void**)&wh, g_wh);
    cudaGetSymbolAddress((void**)&wl, g_wl);
    cudaGetSymbolAddress((void**)&ch, g_ch);
    cudaGetSymbolAddress((void**)&cl, g_cl);

    cudaFuncSetAttribute(gemm_qkv_kernel, cudaFuncAttributeMaxDynamicSharedMemorySize, GEMM_SMEM);
    cudaFuncSetAttribute(gemm_o_kernel,   cudaFuncAttributeMaxDynamicSharedMemorySize, GEMM_SMEM);
    cudaFuncSetAttribute(attn_mma_kernel, cudaFuncAttributeMaxDynamicSharedMemorySize, ATT_SMEM);

    // launch order: gemm_o is the 4th launch -> lands in the ncu capture slot
    cvt_all_kernel<<<(CVT_TOTAL + 255) / 256, 256>>>(                         // 1
        x, wq, wk, wv, wo, xh, xl, wh, wl);

    gemm_qkv_kernel<<<dim3(DD / 128, MM / 128, 3), GEMM_THREADS, GEMM_SMEM>>>(// 2
        xh, xl, wh, wl, qh, ql, kh, kl, vh, vl);

    attn_mma_kernel<<<dim3(SS / 128, BB * HH), 256, ATT_SMEM>>>(              // 3
        qh, ql, kh, kl, vh, vl, ch, cl);

    gemm_o_kernel<<<dim3(DD / 128, MM / 128), GEMM_THREADS, GEMM_SMEM>>>(     // 4
        ch, cl, wh + (size_t)3 * DD * DD, wl + (size_t)3 * DD * DD, bo, out);
}